// round 16
// baseline (speedup 1.0000x reference)
#include <cuda_runtime.h>
#include <cuda_bf16.h>
#include <cstdint>

#define N_NODES 10000
#define M_PAD   10112        // 79 * 128
#define N_EDGES 320000
#define N_GRAPHS 64
#define DIM 256
#define A_DIM 118
#define A_PAD 128
#define OUT_DIM 100

typedef unsigned long long u64;

// ---------------- scratch (static device globals; no allocation) ----------------
__device__ float g_h[N_NODES * DIM];           // node features (fp32, GEMM output)
__device__ __nv_bfloat16 g_ah[M_PAD * DIM];    // A operand hi (tail stays zero from load)
__device__ __nv_bfloat16 g_al[M_PAD * DIM];    // A operand lo
__device__ __nv_bfloat16 g_wnh[256 * A_PAD];   // W_node^T hi  [n=256][k=128]
__device__ __nv_bfloat16 g_wnl[256 * A_PAD];
__device__ __nv_bfloat16 g_wgh[2 * 256 * DIM]; // W_gnn^T hi  [layer][n=256][k=256]
__device__ __nv_bfloat16 g_wgl[2 * 256 * DIM];
__device__ float g_feat[N_GRAPHS * DIM];
__device__ int   g_deg[N_NODES];               // zero at load; scan resets each call
__device__ int   g_off[N_NODES + 1];
__device__ int   g_cursor[N_NODES];
__device__ int2  g_edge[N_EDGES];              // {src<<10 (byte offset), len bits} in CSR(dst) order

__device__ __forceinline__ uint32_t smem_u32(const void* p) {
    uint32_t a;
    asm("{ .reg .u64 t; cvta.to.shared.u64 t, %1; cvt.u32.u64 %0, t; }" : "=r"(a) : "l"(p));
    return a;
}
__device__ __forceinline__ void bf_split(float x, __nv_bfloat16& h, __nv_bfloat16& l) {
    h = __float2bfloat16(x);
    l = __float2bfloat16(x - __bfloat162float(h));
}
// packed f32x2 ops
__device__ __forceinline__ u64 fma2(u64 a, u64 b, u64 c) {
    u64 d; asm("fma.rn.f32x2 %0, %1, %2, %3;" : "=l"(d) : "l"(a), "l"(b), "l"(c)); return d;
}
__device__ __forceinline__ u64 add2(u64 a, u64 b) {
    u64 d; asm("add.rn.f32x2 %0, %1, %2;" : "=l"(d) : "l"(a), "l"(b)); return d;
}

// ---------------- fused setup: conv_a (x4 per thread) + conv_w x3 ----------------
#define NB_CONVA 1264                 // 1264*256*4 = 1294336 >= M_PAD*A_PAD
#define NB_CONVW_N 128
#define NB_CONVW_G 256
#define NB_SETUP (NB_CONVA + NB_CONVW_N + 2 * NB_CONVW_G)

__device__ __forceinline__ void conv_w_body(const float* __restrict__ W,
                                            __nv_bfloat16* __restrict__ oh,
                                            __nv_bfloat16* __restrict__ ol,
                                            int Ksrc, int Kpad, int i) {
    int n = i / Kpad, k = i % Kpad;
    float x = (k < Ksrc) ? W[k * 256 + n] : 0.f;
    __nv_bfloat16 h, l;
    bf_split(x, h, l);
    oh[i] = h;
    ol[i] = l;
}

__global__ void setup_kernel(const float* __restrict__ A,
                             const float* __restrict__ Wn,
                             const float* __restrict__ Wg) {
    int b = blockIdx.x;
    int t = threadIdx.x;
    if (b < NB_CONVA) {
        int i0 = (b * 256 + t) * 4;   // 4 consecutive elems in padded [M_PAD,128] view
        int r = i0 >> 7;
        int k0 = i0 & 127;            // 4-aligned, stays within one row
        __nv_bfloat16 hs[4], ls[4];
#pragma unroll
        for (int u = 0; u < 4; u++) {
            int k = k0 + u;
            float x = (r < N_NODES && k < A_DIM) ? A[r * A_DIM + k] : 0.f;
            bf_split(x, hs[u], ls[u]);
        }
        if (i0 < M_PAD * A_PAD) {
            *(uint2*)&g_ah[i0] = *(const uint2*)hs;
            *(uint2*)&g_al[i0] = *(const uint2*)ls;
        }
        return;
    }
    b -= NB_CONVA;
    if (b < NB_CONVW_N) {
        conv_w_body(Wn, g_wnh, g_wnl, A_DIM, A_PAD, b * 256 + t);
        return;
    }
    b -= NB_CONVW_N;
    if (b < NB_CONVW_G) {
        conv_w_body(Wg, g_wgh, g_wgl, DIM, DIM, b * 256 + t);
        return;
    }
    b -= NB_CONVW_G;
    conv_w_body(Wg + DIM * DIM, g_wgh + 256 * DIM, g_wgl + 256 * DIM, DIM, DIM, b * 256 + t);
}

// ---------------- CSR build ----------------
__global__ void count_kernel(const int* __restrict__ dst) {
    int j0 = (blockIdx.x * blockDim.x + threadIdx.x) * 4;
    if (j0 >= N_EDGES) return;
    int4 d4 = *(const int4*)(dst + j0);
    atomicAdd(&g_deg[d4.x], 1);
    atomicAdd(&g_deg[d4.y], 1);
    atomicAdd(&g_deg[d4.z], 1);
    atomicAdd(&g_deg[d4.w], 1);
}

__global__ void scan_kernel() {
    __shared__ int sm[1024];
    const int SEQ = 10;
    int t = threadIdx.x;
    int vals[SEQ];
    int tot = 0;
    int base = t * SEQ;
#pragma unroll
    for (int u = 0; u < SEQ; u++) {
        int i = base + u;
        vals[u] = (i < N_NODES) ? g_deg[i] : 0;
        if (i < N_NODES) g_deg[i] = 0;  // reset for next call (graph replay)
        tot += vals[u];
    }
    sm[t] = tot;
    __syncthreads();
    for (int s = 1; s < 1024; s <<= 1) {
        int v = 0;
        if (t >= s) v = sm[t - s];
        __syncthreads();
        if (t >= s) sm[t] += v;
        __syncthreads();
    }
    int run = (t > 0) ? sm[t - 1] : 0;
#pragma unroll
    for (int u = 0; u < SEQ; u++) {
        int i = base + u;
        if (i < N_NODES) {
            g_off[i] = run;
            g_cursor[i] = run;
            run += vals[u];
        }
    }
    if (t == 1023) g_off[N_NODES] = sm[1023];
}

// fill: permute {src<<10, len} payload into CSR(dst) order, one 8B store per edge
__global__ void fill_kernel(const int* __restrict__ dst,
                            const int* __restrict__ src,
                            const float* __restrict__ length) {
    int j0 = (blockIdx.x * blockDim.x + threadIdx.x) * 4;
    if (j0 >= N_EDGES) return;
    int4 d4 = *(const int4*)(dst + j0);
    int4 s4 = *(const int4*)(src + j0);
    float4 l4 = *(const float4*)(length + j0);
    int p0 = atomicAdd(&g_cursor[d4.x], 1);
    int p1 = atomicAdd(&g_cursor[d4.y], 1);
    int p2 = atomicAdd(&g_cursor[d4.z], 1);
    int p3 = atomicAdd(&g_cursor[d4.w], 1);
    g_edge[p0] = make_int2(s4.x << 10, __float_as_int(l4.x));
    g_edge[p1] = make_int2(s4.y << 10, __float_as_int(l4.y));
    g_edge[p2] = make_int2(s4.z << 10, __float_as_int(l4.z));
    g_edge[p3] = make_int2(s4.w << 10, __float_as_int(l4.w));
}

// ---------------- GINE aggregation (packed math, pre-shifted offsets) ----------------
__global__ __launch_bounds__(64, 32) void agg_kernel(
                           const float* __restrict__ We,
                           const float* __restrict__ be,
                           const float* __restrict__ geps,
                           int layer) {
    int node = blockIdx.x;
    int q = threadIdx.x;  // 64 threads x 4 channels
    float4 wef = ((const float4*)We)[q];
    float4 bbf = ((const float4*)be)[q];
    const u64 we01 = ((const u64*)&wef)[0];
    const u64 we23 = ((const u64*)&wef)[1];
    const u64 bb01 = ((const u64*)&bbf)[0];
    const u64 bb23 = ((const u64*)&bbf)[1];
    int lo = g_off[node];
    int hi = g_off[node + 1];
    const char* hbase = (const char*)g_h + q * 16;   // q-channel base
    __shared__ int   s_off[64];
    __shared__ float s_len[64];
    u64 acc01 = 0ull, acc23 = 0ull;
    for (int base = lo; base < hi; base += 64) {
        int cnt = min(64, hi - base);
        if (q < cnt) {
            int2 e = g_edge[base + q];
            s_off[q] = e.x;
            s_len[q] = __int_as_float(e.y);
        }
        __syncthreads();
#pragma unroll 8
        for (int k = 0; k < cnt; k++) {
            float lk = s_len[k];
            float2 lp = make_float2(lk, lk);
            u64 ll = *(const u64*)&lp;
            float4 hv = *(const float4*)(hbase + s_off[k]);
            u64 h01 = ((const u64*)&hv)[0];
            u64 h23 = ((const u64*)&hv)[1];
            u64 m01 = add2(h01, fma2(ll, we01, bb01));
            u64 m23 = add2(h23, fma2(ll, we23, bb23));
            float2 f01 = *(const float2*)&m01;
            float2 f23 = *(const float2*)&m23;
            float2 r01 = make_float2(fmaxf(f01.x, 0.f), fmaxf(f01.y, 0.f));
            float2 r23 = make_float2(fmaxf(f23.x, 0.f), fmaxf(f23.y, 0.f));
            acc01 = add2(acc01, *(const u64*)&r01);
            acc23 = add2(acc23, *(const u64*)&r23);
        }
        __syncthreads();
    }
    float e1 = 1.f + geps[layer];
    const float4 h0 = *(const float4*)&g_h[(size_t)node * DIM + q * 4];
    float2 a01 = *(const float2*)&acc01;
    float2 a23 = *(const float2*)&acc23;
    float xs[4] = {e1 * h0.x + a01.x, e1 * h0.y + a01.y,
                   e1 * h0.z + a23.x, e1 * h0.w + a23.y};
    size_t o = (size_t)node * DIM + q * 4;
#pragma unroll
    for (int u = 0; u < 4; u++) {
        __nv_bfloat16 h, l;
        bf_split(xs[u], h, l);
        g_ah[o + u] = h;
        g_al[o + u] = l;
    }
}

// ---------------- mma.sync bf16 split GEMM, 128x64 tiles, 2 CTA/SM ----------------
#define SROW 144                         // bytes per smem row (64 bf16 + 8 pad)
#define A_TILE_B (128 * SROW)            // 18432
#define B_TILE_B (64 * SROW)             // 9216
#define SMO_AH 0
#define SMO_AL A_TILE_B
#define SMO_BH (2 * A_TILE_B)
#define SMO_BL (2 * A_TILE_B + B_TILE_B)
#define STAGE_BYTES (2 * A_TILE_B + 2 * B_TILE_B)   // 55296
#define MMA_SMEM (2 * STAGE_BYTES)                  // 110592

#define CP_ASYNC16(sa, gp) \
    asm volatile("cp.async.cg.shared.global [%0], [%1], 16;" :: "r"(sa), "l"(gp))
#define CP_COMMIT() asm volatile("cp.async.commit_group;" ::: "memory")
#define CP_WAIT1() asm volatile("cp.async.wait_group 1;" ::: "memory")
#define CP_WAIT0() asm volatile("cp.async.wait_group 0;" ::: "memory")

__device__ __forceinline__ void ldsm4(uint32_t* r, uint32_t addr) {
    asm volatile("ldmatrix.sync.aligned.m8n8.x4.shared.b16 {%0,%1,%2,%3}, [%4];"
                 : "=r"(r[0]), "=r"(r[1]), "=r"(r[2]), "=r"(r[3]) : "r"(addr));
}
__device__ __forceinline__ void mma16816(float* d, const uint32_t* a, const uint32_t* b) {
    asm volatile(
        "mma.sync.aligned.m16n8k16.row.col.f32.bf16.bf16.f32 "
        "{%0,%1,%2,%3}, {%4,%5,%6,%7}, {%8,%9}, {%0,%1,%2,%3};"
        : "+f"(d[0]), "+f"(d[1]), "+f"(d[2]), "+f"(d[3])
        : "r"(a[0]), "r"(a[1]), "r"(a[2]), "r"(a[3]), "r"(b[0]), "r"(b[1]));
}

__global__ __launch_bounds__(256, 2) void mma_gemm_kernel(
    const __nv_bfloat16* __restrict__ Ah, const __nv_bfloat16* __restrict__ Al,
    int K,  // 128 or 256 (== row stride of A and B)
    const __nv_bfloat16* __restrict__ Bh, const __nv_bfloat16* __restrict__ Bl,
    const float* __restrict__ bias, float* __restrict__ C) {
    extern __shared__ char sm[];
    uint32_t sbase = smem_u32(sm);
    int tid = threadIdx.x;
    int wid = tid >> 5;
    int lid = tid & 31;
    int bm = blockIdx.y * 128;
    int bn = blockIdx.x * 64;
    int wm = (wid >> 1) * 32;  // 0,32,64,96
    int wn = (wid & 1) * 32;   // 0,32

    float acc[2][4][4];
#pragma unroll
    for (int i = 0; i < 2; i++)
#pragma unroll
        for (int j = 0; j < 4; j++)
#pragma unroll
            for (int u = 0; u < 4; u++) acc[i][j][u] = 0.f;

    const int lm_arow = ((lid >> 3) & 1) * 8 + (lid & 7);
    const int lm_ak   = ((lid >> 4) & 1) * 8;
    const int lm_bn   = ((lid >> 4) & 1) * 8 + (lid & 7);
    const int lm_bk   = ((lid >> 3) & 1) * 8;

    const int nchunk = K >> 6;

    auto load_stage = [&](int c, int st) {
        uint32_t sb = sbase + st * STAGE_BYTES;
#pragma unroll
        for (int i = tid; i < 1024; i += 256) {
            int row = i >> 3;
            int ch = i & 7;
            uint32_t so = row * SROW + ch * 16;
            size_t go = (size_t)(bm + row) * K + c * 64 + ch * 8;
            CP_ASYNC16(sb + SMO_AH + so, Ah + go);
            CP_ASYNC16(sb + SMO_AL + so, Al + go);
        }
#pragma unroll
        for (int i = tid; i < 512; i += 256) {
            int row = i >> 3;
            int ch = i & 7;
            uint32_t so = row * SROW + ch * 16;
            size_t go = (size_t)(bn + row) * K + c * 64 + ch * 8;
            CP_ASYNC16(sb + SMO_BH + so, Bh + go);
            CP_ASYNC16(sb + SMO_BL + so, Bl + go);
        }
    };

    load_stage(0, 0);
    CP_COMMIT();

    for (int c = 0; c < nchunk; c++) {
        int st = c & 1;
        if (c + 1 < nchunk) {
            load_stage(c + 1, st ^ 1);
            CP_COMMIT();
            CP_WAIT1();
        } else {
            CP_WAIT0();
        }
        __syncthreads();

        uint32_t sb = sbase + st * STAGE_BYTES;
#pragma unroll
        for (int ks = 0; ks < 4; ks++) {
            int k0 = ks * 16;
            uint32_t ah[2][4], al[2][4], bh[2][4], bl[2][4];
#pragma unroll
            for (int mf = 0; mf < 2; mf++) {
                uint32_t off = (uint32_t)((wm + mf * 16 + lm_arow) * SROW + (k0 + lm_ak) * 2);
                ldsm4(ah[mf], sb + SMO_AH + off);
                ldsm4(al[mf], sb + SMO_AL + off);
            }
#pragma unroll
            for (int nf2 = 0; nf2 < 2; nf2++) {
                uint32_t off = (uint32_t)((wn + nf2 * 16 + lm_bn) * SROW + (k0 + lm_bk) * 2);
                ldsm4(bh[nf2], sb + SMO_BH + off);
                ldsm4(bl[nf2], sb + SMO_BL + off);
            }
#pragma unroll
            for (int mf = 0; mf < 2; mf++)
#pragma unroll
                for (int nf = 0; nf < 4; nf++) {
                    const uint32_t* pbh = &bh[nf >> 1][(nf & 1) * 2];
                    const uint32_t* pbl = &bl[nf >> 1][(nf & 1) * 2];
                    mma16816(acc[mf][nf], ah[mf], pbh);
                    mma16816(acc[mf][nf], ah[mf], pbl);
                    mma16816(acc[mf][nf], al[mf], pbh);
                }
        }
        __syncthreads();
    }

    // epilogue: float2 stores
#pragma unroll
    for (int mf = 0; mf < 2; mf++) {
        int r0 = bm + wm + mf * 16 + (lid >> 2);
#pragma unroll
        for (int nf = 0; nf < 4; nf++) {
            int col = bn + wn + nf * 8 + (lid & 3) * 2;
            float b0 = bias[col], b1 = bias[col + 1];
            if (r0 < N_NODES) {
                float2 v = make_float2(acc[mf][nf][0] + b0, acc[mf][nf][1] + b1);
                *(float2*)&C[(size_t)r0 * DIM + col] = v;
            }
            if (r0 + 8 < N_NODES) {
                float2 v = make_float2(acc[mf][nf][2] + b0, acc[mf][nf][3] + b1);
                *(float2*)&C[(size_t)(r0 + 8) * DIM + col] = v;
            }
        }
    }
}

// ---------------- pooling ----------------
__global__ __launch_bounds__(256) void pool_kernel(const int* __restrict__ gid) {
    int g = blockIdx.x;
    int d = threadIdx.x;
    int lo = 0, hi = N_NODES;
    while (lo < hi) { int m = (lo + hi) >> 1; if (gid[m] < g) lo = m + 1; else hi = m; }
    int start = lo;
    lo = 0; hi = N_NODES;
    while (lo < hi) { int m = (lo + hi) >> 1; if (gid[m] < g + 1) lo = m + 1; else hi = m; }
    int end = lo;
    float acc = 0.f;
#pragma unroll 8
    for (int i = start; i < end; i++) acc += g_h[(size_t)i * DIM + d];
    g_feat[g * DIM + d] = acc;
}

// ---------------- fused minmax + normalize + MLP head ----------------
__global__ void head_kernel(const float* __restrict__ Wm,
                            const float* __restrict__ bm,
                            const float* __restrict__ epsp,
                            float* __restrict__ out) {
    int g = blockIdx.x;
    int t = threadIdx.x;  // 256 threads
    __shared__ float smn[8], smx[8];
    __shared__ float sf[DIM];
    float mn = 3.4e38f, mx = -3.4e38f;
    for (int i = t; i < N_GRAPHS * DIM; i += 256) {
        float v = g_feat[i];
        mn = fminf(mn, v);
        mx = fmaxf(mx, v);
    }
#pragma unroll
    for (int s = 16; s > 0; s >>= 1) {
        mn = fminf(mn, __shfl_xor_sync(0xFFFFFFFFu, mn, s));
        mx = fmaxf(mx, __shfl_xor_sync(0xFFFFFFFFu, mx, s));
    }
    if ((t & 31) == 0) { smn[t >> 5] = mn; smx[t >> 5] = mx; }
    __syncthreads();
    if (t == 0) {
        float a = smn[0], b = smx[0];
#pragma unroll
        for (int i = 1; i < 8; i++) {
            a = fminf(a, smn[i]);
            b = fmaxf(b, smx[i]);
        }
        smn[0] = a;
        smx[0] = b;
    }
    __syncthreads();
    mn = smn[0];
    mx = smx[0];
    float inv = 1.f / (epsp[0] + mx - mn);
    if (t < DIM) sf[t] = (g_feat[g * DIM + t] - mn) * inv;
    __syncthreads();
    if (t < OUT_DIM) {
        float acc = bm[t];
#pragma unroll 8
        for (int d = 0; d < DIM; d++) acc += sf[d] * Wm[d * OUT_DIM + t];
        out[g * OUT_DIM + t] = acc;
    }
}

// ---------------- launch ----------------
extern "C" void kernel_launch(void* const* d_in, const int* in_sizes, int n_in,
                              void* d_out, int out_size) {
    const float* atomic_num = (const float*)d_in[0];
    const float* length     = (const float*)d_in[1];
    const int*   src        = (const int*)d_in[2];
    const int*   dst        = (const int*)d_in[3];
    const int*   graph_ids  = (const int*)d_in[4];
    const float* W_node     = (const float*)d_in[5];
    const float* b_node     = (const float*)d_in[6];
    const float* W_edge     = (const float*)d_in[7];
    const float* b_edge     = (const float*)d_in[8];
    const float* gine_eps   = (const float*)d_in[9];
    const float* W_gnn      = (const float*)d_in[10];
    const float* b_gnn      = (const float*)d_in[11];
    const float* eps_param  = (const float*)d_in[12];
    const float* W_mlp      = (const float*)d_in[13];
    const float* b_mlp      = (const float*)d_in[14];
    float* out = (float*)d_out;

    float* ph;
    cudaGetSymbolAddress((void**)&ph, g_h);
    __nv_bfloat16 *pah, *pal, *pwnh, *pwnl, *pwgh, *pwgl;
    cudaGetSymbolAddress((void**)&pah, g_ah);
    cudaGetSymbolAddress((void**)&pal, g_al);
    cudaGetSymbolAddress((void**)&pwnh, g_wnh);
    cudaGetSymbolAddress((void**)&pwnl, g_wnl);
    cudaGetSymbolAddress((void**)&pwgh, g_wgh);
    cudaGetSymbolAddress((void**)&pwgl, g_wgl);

    cudaFuncSetAttribute(mma_gemm_kernel, cudaFuncAttributeMaxDynamicSharedMemorySize, MMA_SMEM);

    // lazy-init side stream + fork/join events
    static cudaStream_t s2 = nullptr;
    static cudaEvent_t evFork = nullptr, evJoin = nullptr;
    if (!s2) {
        cudaStreamCreateWithFlags(&s2, cudaStreamNonBlocking);
        cudaEventCreateWithFlags(&evFork, cudaEventDisableTiming);
        cudaEventCreateWithFlags(&evJoin, cudaEventDisableTiming);
    }

    // fork: CSR build on s2, conversions + GEMM-0 on main stream (independent)
    cudaEventRecord(evFork, 0);
    cudaStreamWaitEvent(s2, evFork, 0);
    count_kernel<<<(N_EDGES / 4 + 255) / 256, 256, 0, s2>>>(dst);
    scan_kernel<<<1, 1024, 0, s2>>>();
    fill_kernel<<<(N_EDGES / 4 + 255) / 256, 256, 0, s2>>>(dst, src, length);
    cudaEventRecord(evJoin, s2);

    setup_kernel<<<NB_SETUP, 256>>>(atomic_num, W_node, W_gnn);

    dim3 ggrid(4, M_PAD / 128);

    // node embedding: h = atomic_num @ W_node + b_node
    mma_gemm_kernel<<<ggrid, 256, MMA_SMEM>>>(pah, pal, A_PAD, pwnh, pwnl, b_node, ph);

    // join: agg needs the CSR
    cudaStreamWaitEvent(0, evJoin, 0);

    // GINE layers
    for (int layer = 0; layer < 2; layer++) {
        agg_kernel<<<N_NODES, 64>>>(W_edge, b_edge, gine_eps, layer);
        mma_gemm_kernel<<<ggrid, 256, MMA_SMEM>>>(pah, pal, DIM,
                                                  pwgh + layer * 256 * DIM,
                                                  pwgl + layer * 256 * DIM,
                                                  b_gnn + layer * DIM, ph);
    }

    // pooling + fused normalize/head
    pool_kernel<<<N_GRAPHS, 256>>>(graph_ids);
    head_kernel<<<N_GRAPHS, 256>>>(W_mlp, b_mlp, eps_param, out);
}

// round 17
// speedup vs baseline: 1.0300x; 1.0300x over previous
#include <cuda_runtime.h>
#include <cuda_bf16.h>
#include <cstdint>

#define N_NODES 10000
#define M_PAD   10112        // 79 * 128
#define N_EDGES 320000
#define N_GRAPHS 64
#define DIM 256
#define A_DIM 118
#define A_PAD 128
#define OUT_DIM 100

typedef unsigned long long u64;

// ---------------- scratch (static device globals; no allocation) ----------------
__device__ float g_h[N_NODES * DIM];           // node features (fp32, GEMM output)
__device__ __nv_bfloat16 g_ah[M_PAD * DIM];    // A operand hi (tail stays zero from load)
__device__ __nv_bfloat16 g_al[M_PAD * DIM];    // A operand lo
__device__ __nv_bfloat16 g_wnh[256 * A_PAD];   // W_node^T hi  [n=256][k=128]
__device__ __nv_bfloat16 g_wnl[256 * A_PAD];
__device__ __nv_bfloat16 g_wgh[2 * 256 * DIM]; // W_gnn^T hi  [layer][n=256][k=256]
__device__ __nv_bfloat16 g_wgl[2 * 256 * DIM];
__device__ float g_feat[N_GRAPHS * DIM];
__device__ int   g_deg[N_NODES];               // zero at load; scan resets each call
__device__ int   g_off[N_NODES + 1];
__device__ int   g_cursor[N_NODES];
__device__ int2  g_edge[N_EDGES];              // {src<<10 (byte offset), len bits} in CSR(dst) order

__device__ __forceinline__ uint32_t smem_u32(const void* p) {
    uint32_t a;
    asm("{ .reg .u64 t; cvta.to.shared.u64 t, %1; cvt.u32.u64 %0, t; }" : "=r"(a) : "l"(p));
    return a;
}
__device__ __forceinline__ void bf_split(float x, __nv_bfloat16& h, __nv_bfloat16& l) {
    h = __float2bfloat16(x);
    l = __float2bfloat16(x - __bfloat162float(h));
}
// packed f32x2 ops
__device__ __forceinline__ u64 fma2(u64 a, u64 b, u64 c) {
    u64 d; asm("fma.rn.f32x2 %0, %1, %2, %3;" : "=l"(d) : "l"(a), "l"(b), "l"(c)); return d;
}
__device__ __forceinline__ u64 add2(u64 a, u64 b) {
    u64 d; asm("add.rn.f32x2 %0, %1, %2;" : "=l"(d) : "l"(a), "l"(b)); return d;
}

// ---------------- fused setup: conv_a (x4 per thread) + conv_w x3 ----------------
#define NB_CONVA 1264                 // 1264*256*4 = 1294336 >= M_PAD*A_PAD
#define NB_CONVW_N 128
#define NB_CONVW_G 256
#define NB_SETUP (NB_CONVA + NB_CONVW_N + 2 * NB_CONVW_G)

__device__ __forceinline__ void conv_w_body(const float* __restrict__ W,
                                            __nv_bfloat16* __restrict__ oh,
                                            __nv_bfloat16* __restrict__ ol,
                                            int Ksrc, int Kpad, int i) {
    int n = i / Kpad, k = i % Kpad;
    float x = (k < Ksrc) ? W[k * 256 + n] : 0.f;
    __nv_bfloat16 h, l;
    bf_split(x, h, l);
    oh[i] = h;
    ol[i] = l;
}

__global__ void setup_kernel(const float* __restrict__ A,
                             const float* __restrict__ Wn,
                             const float* __restrict__ Wg) {
    int b = blockIdx.x;
    int t = threadIdx.x;
    if (b < NB_CONVA) {
        int i0 = (b * 256 + t) * 4;   // 4 consecutive elems in padded [M_PAD,128] view
        int r = i0 >> 7;
        int k0 = i0 & 127;            // 4-aligned, stays within one row
        __nv_bfloat16 hs[4], ls[4];
#pragma unroll
        for (int u = 0; u < 4; u++) {
            int k = k0 + u;
            float x = (r < N_NODES && k < A_DIM) ? A[r * A_DIM + k] : 0.f;
            bf_split(x, hs[u], ls[u]);
        }
        if (i0 < M_PAD * A_PAD) {
            *(uint2*)&g_ah[i0] = *(const uint2*)hs;
            *(uint2*)&g_al[i0] = *(const uint2*)ls;
        }
        return;
    }
    b -= NB_CONVA;
    if (b < NB_CONVW_N) {
        conv_w_body(Wn, g_wnh, g_wnl, A_DIM, A_PAD, b * 256 + t);
        return;
    }
    b -= NB_CONVW_N;
    if (b < NB_CONVW_G) {
        conv_w_body(Wg, g_wgh, g_wgl, DIM, DIM, b * 256 + t);
        return;
    }
    b -= NB_CONVW_G;
    conv_w_body(Wg + DIM * DIM, g_wgh + 256 * DIM, g_wgl + 256 * DIM, DIM, DIM, b * 256 + t);
}

// ---------------- CSR build ----------------
__global__ void count_kernel(const int* __restrict__ dst) {
    int j0 = (blockIdx.x * blockDim.x + threadIdx.x) * 4;
    if (j0 >= N_EDGES) return;
    int4 d4 = *(const int4*)(dst + j0);
    atomicAdd(&g_deg[d4.x], 1);
    atomicAdd(&g_deg[d4.y], 1);
    atomicAdd(&g_deg[d4.z], 1);
    atomicAdd(&g_deg[d4.w], 1);
}

__global__ void scan_kernel() {
    __shared__ int sm[1024];
    const int SEQ = 10;
    int t = threadIdx.x;
    int vals[SEQ];
    int tot = 0;
    int base = t * SEQ;
#pragma unroll
    for (int u = 0; u < SEQ; u++) {
        int i = base + u;
        vals[u] = (i < N_NODES) ? g_deg[i] : 0;
        if (i < N_NODES) g_deg[i] = 0;  // reset for next call (graph replay)
        tot += vals[u];
    }
    sm[t] = tot;
    __syncthreads();
    for (int s = 1; s < 1024; s <<= 1) {
        int v = 0;
        if (t >= s) v = sm[t - s];
        __syncthreads();
        if (t >= s) sm[t] += v;
        __syncthreads();
    }
    int run = (t > 0) ? sm[t - 1] : 0;
#pragma unroll
    for (int u = 0; u < SEQ; u++) {
        int i = base + u;
        if (i < N_NODES) {
            g_off[i] = run;
            g_cursor[i] = run;
            run += vals[u];
        }
    }
    if (t == 1023) g_off[N_NODES] = sm[1023];
}

// fill: permute {src<<10, len} payload into CSR(dst) order, one 8B store per edge
__global__ void fill_kernel(const int* __restrict__ dst,
                            const int* __restrict__ src,
                            const float* __restrict__ length) {
    int j0 = (blockIdx.x * blockDim.x + threadIdx.x) * 4;
    if (j0 >= N_EDGES) return;
    int4 d4 = *(const int4*)(dst + j0);
    int4 s4 = *(const int4*)(src + j0);
    float4 l4 = *(const float4*)(length + j0);
    int p0 = atomicAdd(&g_cursor[d4.x], 1);
    int p1 = atomicAdd(&g_cursor[d4.y], 1);
    int p2 = atomicAdd(&g_cursor[d4.z], 1);
    int p3 = atomicAdd(&g_cursor[d4.w], 1);
    g_edge[p0] = make_int2(s4.x << 10, __float_as_int(l4.x));
    g_edge[p1] = make_int2(s4.y << 10, __float_as_int(l4.y));
    g_edge[p2] = make_int2(s4.z << 10, __float_as_int(l4.z));
    g_edge[p3] = make_int2(s4.w << 10, __float_as_int(l4.w));
}

// ---------------- GINE aggregation (packed math, pre-shifted offsets) ----------------
__global__ void agg_kernel(const float* __restrict__ We,
                           const float* __restrict__ be,
                           const float* __restrict__ geps,
                           int layer) {
    int node = blockIdx.x;
    int q = threadIdx.x;  // 64 threads x 4 channels
    float4 wef = ((const float4*)We)[q];
    float4 bbf = ((const float4*)be)[q];
    const u64 we01 = ((const u64*)&wef)[0];
    const u64 we23 = ((const u64*)&wef)[1];
    const u64 bb01 = ((const u64*)&bbf)[0];
    const u64 bb23 = ((const u64*)&bbf)[1];
    int lo = g_off[node];
    int hi = g_off[node + 1];
    const char* hbase = (const char*)g_h + q * 16;   // q-channel base
    __shared__ int   s_off[64];
    __shared__ float s_len[64];
    u64 acc01 = 0ull, acc23 = 0ull;
    for (int base = lo; base < hi; base += 64) {
        int cnt = min(64, hi - base);
        if (q < cnt) {
            int2 e = g_edge[base + q];
            s_off[q] = e.x;
            s_len[q] = __int_as_float(e.y);
        }
        __syncthreads();
#pragma unroll 8
        for (int k = 0; k < cnt; k++) {
            float lk = s_len[k];
            float2 lp = make_float2(lk, lk);
            u64 ll = *(const u64*)&lp;
            float4 hv = *(const float4*)(hbase + s_off[k]);
            u64 h01 = ((const u64*)&hv)[0];
            u64 h23 = ((const u64*)&hv)[1];
            u64 m01 = add2(h01, fma2(ll, we01, bb01));
            u64 m23 = add2(h23, fma2(ll, we23, bb23));
            float2 f01 = *(const float2*)&m01;
            float2 f23 = *(const float2*)&m23;
            float2 r01 = make_float2(fmaxf(f01.x, 0.f), fmaxf(f01.y, 0.f));
            float2 r23 = make_float2(fmaxf(f23.x, 0.f), fmaxf(f23.y, 0.f));
            acc01 = add2(acc01, *(const u64*)&r01);
            acc23 = add2(acc23, *(const u64*)&r23);
        }
        __syncthreads();
    }
    float e1 = 1.f + geps[layer];
    const float4 h0 = *(const float4*)&g_h[(size_t)node * DIM + q * 4];
    float2 a01 = *(const float2*)&acc01;
    float2 a23 = *(const float2*)&acc23;
    float xs[4] = {e1 * h0.x + a01.x, e1 * h0.y + a01.y,
                   e1 * h0.z + a23.x, e1 * h0.w + a23.y};
    size_t o = (size_t)node * DIM + q * 4;
#pragma unroll
    for (int u = 0; u < 4; u++) {
        __nv_bfloat16 h, l;
        bf_split(xs[u], h, l);
        g_ah[o + u] = h;
        g_al[o + u] = l;
    }
}

// ---------------- mma.sync bf16 split GEMM, 128x64 tiles, 2 CTA/SM ----------------
#define SROW 144                         // bytes per smem row (64 bf16 + 8 pad)
#define A_TILE_B (128 * SROW)            // 18432
#define B_TILE_B (64 * SROW)             // 9216
#define SMO_AH 0
#define SMO_AL A_TILE_B
#define SMO_BH (2 * A_TILE_B)
#define SMO_BL (2 * A_TILE_B + B_TILE_B)
#define STAGE_BYTES (2 * A_TILE_B + 2 * B_TILE_B)   // 55296
#define MMA_SMEM (2 * STAGE_BYTES)                  // 110592

#define CP_ASYNC16(sa, gp) \
    asm volatile("cp.async.cg.shared.global [%0], [%1], 16;" :: "r"(sa), "l"(gp))
#define CP_COMMIT() asm volatile("cp.async.commit_group;" ::: "memory")
#define CP_WAIT1() asm volatile("cp.async.wait_group 1;" ::: "memory")
#define CP_WAIT0() asm volatile("cp.async.wait_group 0;" ::: "memory")

__device__ __forceinline__ void ldsm4(uint32_t* r, uint32_t addr) {
    asm volatile("ldmatrix.sync.aligned.m8n8.x4.shared.b16 {%0,%1,%2,%3}, [%4];"
                 : "=r"(r[0]), "=r"(r[1]), "=r"(r[2]), "=r"(r[3]) : "r"(addr));
}
__device__ __forceinline__ void mma16816(float* d, const uint32_t* a, const uint32_t* b) {
    asm volatile(
        "mma.sync.aligned.m16n8k16.row.col.f32.bf16.bf16.f32 "
        "{%0,%1,%2,%3}, {%4,%5,%6,%7}, {%8,%9}, {%0,%1,%2,%3};"
        : "+f"(d[0]), "+f"(d[1]), "+f"(d[2]), "+f"(d[3])
        : "r"(a[0]), "r"(a[1]), "r"(a[2]), "r"(a[3]), "r"(b[0]), "r"(b[1]));
}

__global__ __launch_bounds__(256, 2) void mma_gemm_kernel(
    const __nv_bfloat16* __restrict__ Ah, const __nv_bfloat16* __restrict__ Al,
    int K,  // 128 or 256 (== row stride of A and B)
    const __nv_bfloat16* __restrict__ Bh, const __nv_bfloat16* __restrict__ Bl,
    const float* __restrict__ bias, float* __restrict__ C) {
    extern __shared__ char sm[];
    uint32_t sbase = smem_u32(sm);
    int tid = threadIdx.x;
    int wid = tid >> 5;
    int lid = tid & 31;
    int bm = blockIdx.y * 128;
    int bn = blockIdx.x * 64;
    int wm = (wid >> 1) * 32;  // 0,32,64,96
    int wn = (wid & 1) * 32;   // 0,32

    float acc[2][4][4];
#pragma unroll
    for (int i = 0; i < 2; i++)
#pragma unroll
        for (int j = 0; j < 4; j++)
#pragma unroll
            for (int u = 0; u < 4; u++) acc[i][j][u] = 0.f;

    const int lm_arow = ((lid >> 3) & 1) * 8 + (lid & 7);
    const int lm_ak   = ((lid >> 4) & 1) * 8;
    const int lm_bn   = ((lid >> 4) & 1) * 8 + (lid & 7);
    const int lm_bk   = ((lid >> 3) & 1) * 8;

    const int nchunk = K >> 6;

    auto load_stage = [&](int c, int st) {
        uint32_t sb = sbase + st * STAGE_BYTES;
#pragma unroll
        for (int i = tid; i < 1024; i += 256) {
            int row = i >> 3;
            int ch = i & 7;
            uint32_t so = row * SROW + ch * 16;
            size_t go = (size_t)(bm + row) * K + c * 64 + ch * 8;
            CP_ASYNC16(sb + SMO_AH + so, Ah + go);
            CP_ASYNC16(sb + SMO_AL + so, Al + go);
        }
#pragma unroll
        for (int i = tid; i < 512; i += 256) {
            int row = i >> 3;
            int ch = i & 7;
            uint32_t so = row * SROW + ch * 16;
            size_t go = (size_t)(bn + row) * K + c * 64 + ch * 8;
            CP_ASYNC16(sb + SMO_BH + so, Bh + go);
            CP_ASYNC16(sb + SMO_BL + so, Bl + go);
        }
    };

    load_stage(0, 0);
    CP_COMMIT();

    for (int c = 0; c < nchunk; c++) {
        int st = c & 1;
        if (c + 1 < nchunk) {
            load_stage(c + 1, st ^ 1);
            CP_COMMIT();
            CP_WAIT1();
        } else {
            CP_WAIT0();
        }
        __syncthreads();

        uint32_t sb = sbase + st * STAGE_BYTES;
#pragma unroll
        for (int ks = 0; ks < 4; ks++) {
            int k0 = ks * 16;
            uint32_t ah[2][4], al[2][4], bh[2][4], bl[2][4];
#pragma unroll
            for (int mf = 0; mf < 2; mf++) {
                uint32_t off = (uint32_t)((wm + mf * 16 + lm_arow) * SROW + (k0 + lm_ak) * 2);
                ldsm4(ah[mf], sb + SMO_AH + off);
                ldsm4(al[mf], sb + SMO_AL + off);
            }
#pragma unroll
            for (int nf2 = 0; nf2 < 2; nf2++) {
                uint32_t off = (uint32_t)((wn + nf2 * 16 + lm_bn) * SROW + (k0 + lm_bk) * 2);
                ldsm4(bh[nf2], sb + SMO_BH + off);
                ldsm4(bl[nf2], sb + SMO_BL + off);
            }
#pragma unroll
            for (int mf = 0; mf < 2; mf++)
#pragma unroll
                for (int nf = 0; nf < 4; nf++) {
                    const uint32_t* pbh = &bh[nf >> 1][(nf & 1) * 2];
                    const uint32_t* pbl = &bl[nf >> 1][(nf & 1) * 2];
                    mma16816(acc[mf][nf], ah[mf], pbh);
                    mma16816(acc[mf][nf], ah[mf], pbl);
                    mma16816(acc[mf][nf], al[mf], pbh);
                }
        }
        __syncthreads();
    }

    // epilogue: float2 stores
#pragma unroll
    for (int mf = 0; mf < 2; mf++) {
        int r0 = bm + wm + mf * 16 + (lid >> 2);
#pragma unroll
        for (int nf = 0; nf < 4; nf++) {
            int col = bn + wn + nf * 8 + (lid & 3) * 2;
            float b0 = bias[col], b1 = bias[col + 1];
            if (r0 < N_NODES) {
                float2 v = make_float2(acc[mf][nf][0] + b0, acc[mf][nf][1] + b1);
                *(float2*)&C[(size_t)r0 * DIM + col] = v;
            }
            if (r0 + 8 < N_NODES) {
                float2 v = make_float2(acc[mf][nf][2] + b0, acc[mf][nf][3] + b1);
                *(float2*)&C[(size_t)(r0 + 8) * DIM + col] = v;
            }
        }
    }
}

// ---------------- pooling ----------------
__global__ void pool_kernel(const int* __restrict__ gid) {
    int g = blockIdx.x;
    int d = threadIdx.x;
    int lo = 0, hi = N_NODES;
    while (lo < hi) { int m = (lo + hi) >> 1; if (gid[m] < g) lo = m + 1; else hi = m; }
    int start = lo;
    lo = 0; hi = N_NODES;
    while (lo < hi) { int m = (lo + hi) >> 1; if (gid[m] < g + 1) lo = m + 1; else hi = m; }
    int end = lo;
    float acc = 0.f;
#pragma unroll 8
    for (int i = start; i < end; i++) acc += g_h[(size_t)i * DIM + d];
    g_feat[g * DIM + d] = acc;
}

// ---------------- fused minmax + normalize + MLP head ----------------
__global__ void head_kernel(const float* __restrict__ Wm,
                            const float* __restrict__ bm,
                            const float* __restrict__ epsp,
                            float* __restrict__ out) {
    int g = blockIdx.x;
    int t = threadIdx.x;  // 256 threads
    __shared__ float smn[8], smx[8];
    __shared__ float sf[DIM];
    float mn = 3.4e38f, mx = -3.4e38f;
    for (int i = t; i < N_GRAPHS * DIM; i += 256) {
        float v = g_feat[i];
        mn = fminf(mn, v);
        mx = fmaxf(mx, v);
    }
#pragma unroll
    for (int s = 16; s > 0; s >>= 1) {
        mn = fminf(mn, __shfl_xor_sync(0xFFFFFFFFu, mn, s));
        mx = fmaxf(mx, __shfl_xor_sync(0xFFFFFFFFu, mx, s));
    }
    if ((t & 31) == 0) { smn[t >> 5] = mn; smx[t >> 5] = mx; }
    __syncthreads();
    if (t == 0) {
        float a = smn[0], b = smx[0];
#pragma unroll
        for (int i = 1; i < 8; i++) {
            a = fminf(a, smn[i]);
            b = fmaxf(b, smx[i]);
        }
        smn[0] = a;
        smx[0] = b;
    }
    __syncthreads();
    mn = smn[0];
    mx = smx[0];
    float inv = 1.f / (epsp[0] + mx - mn);
    if (t < DIM) sf[t] = (g_feat[g * DIM + t] - mn) * inv;
    __syncthreads();
    if (t < OUT_DIM) {
        float acc = bm[t];
#pragma unroll 8
        for (int d = 0; d < DIM; d++) acc += sf[d] * Wm[d * OUT_DIM + t];
        out[g * OUT_DIM + t] = acc;
    }
}

// ---------------- launch ----------------
extern "C" void kernel_launch(void* const* d_in, const int* in_sizes, int n_in,
                              void* d_out, int out_size) {
    const float* atomic_num = (const float*)d_in[0];
    const float* length     = (const float*)d_in[1];
    const int*   src        = (const int*)d_in[2];
    const int*   dst        = (const int*)d_in[3];
    const int*   graph_ids  = (const int*)d_in[4];
    const float* W_node     = (const float*)d_in[5];
    const float* b_node     = (const float*)d_in[6];
    const float* W_edge     = (const float*)d_in[7];
    const float* b_edge     = (const float*)d_in[8];
    const float* gine_eps   = (const float*)d_in[9];
    const float* W_gnn      = (const float*)d_in[10];
    const float* b_gnn      = (const float*)d_in[11];
    const float* eps_param  = (const float*)d_in[12];
    const float* W_mlp      = (const float*)d_in[13];
    const float* b_mlp      = (const float*)d_in[14];
    float* out = (float*)d_out;

    float* ph;
    cudaGetSymbolAddress((void**)&ph, g_h);
    __nv_bfloat16 *pah, *pal, *pwnh, *pwnl, *pwgh, *pwgl;
    cudaGetSymbolAddress((void**)&pah, g_ah);
    cudaGetSymbolAddress((void**)&pal, g_al);
    cudaGetSymbolAddress((void**)&pwnh, g_wnh);
    cudaGetSymbolAddress((void**)&pwnl, g_wnl);
    cudaGetSymbolAddress((void**)&pwgh, g_wgh);
    cudaGetSymbolAddress((void**)&pwgl, g_wgl);

    cudaFuncSetAttribute(mma_gemm_kernel, cudaFuncAttributeMaxDynamicSharedMemorySize, MMA_SMEM);

    // lazy-init side stream + fork/join events
    static cudaStream_t s2 = nullptr;
    static cudaEvent_t evFork = nullptr, evJoin = nullptr;
    if (!s2) {
        cudaStreamCreateWithFlags(&s2, cudaStreamNonBlocking);
        cudaEventCreateWithFlags(&evFork, cudaEventDisableTiming);
        cudaEventCreateWithFlags(&evJoin, cudaEventDisableTiming);
    }

    // fork: CSR build on s2, conversions + GEMM-0 on main stream (independent)
    cudaEventRecord(evFork, 0);
    cudaStreamWaitEvent(s2, evFork, 0);
    count_kernel<<<(N_EDGES / 4 + 255) / 256, 256, 0, s2>>>(dst);
    scan_kernel<<<1, 1024, 0, s2>>>();
    fill_kernel<<<(N_EDGES / 4 + 255) / 256, 256, 0, s2>>>(dst, src, length);
    cudaEventRecord(evJoin, s2);

    setup_kernel<<<NB_SETUP, 256>>>(atomic_num, W_node, W_gnn);

    dim3 ggrid(4, M_PAD / 128);

    // node embedding: h = atomic_num @ W_node + b_node
    mma_gemm_kernel<<<ggrid, 256, MMA_SMEM>>>(pah, pal, A_PAD, pwnh, pwnl, b_node, ph);

    // join: agg needs the CSR
    cudaStreamWaitEvent(0, evJoin, 0);

    // GINE layers
    for (int layer = 0; layer < 2; layer++) {
        agg_kernel<<<N_NODES, 64>>>(W_edge, b_edge, gine_eps, layer);
        mma_gemm_kernel<<<ggrid, 256, MMA_SMEM>>>(pah, pal, DIM,
                                                  pwgh + layer * 256 * DIM,
                                                  pwgl + layer * 256 * DIM,
                                                  b_gnn + layer * DIM, ph);
    }

    // pooling + fused normalize/head
    pool_kernel<<<N_GRAPHS, 256>>>(graph_ids);
    head_kernel<<<N_GRAPHS, 256>>>(W_mlp, b_mlp, eps_param, out);
}